// round 3
// baseline (speedup 1.0000x reference)
#include <cuda_runtime.h>
#include <cstdint>

#define N_NODES 100000
#define FDIM    64

// ---------------- scratch (no allocs allowed) ----------------
__device__ float  g_deg[N_NODES];
__device__ float  g_dis[N_NODES];
__device__ float4 g_xa [N_NODES];          // aggregated 4-dim input features (layer-1, pre-W1)
__device__ float4 g_h  [N_NODES * 16];     // relu output of layer 1 (64 floats = 16 float4 / node)
__device__ float4 g_agg[N_NODES * 16];     // layer-2 aggregation buffer

__device__ __forceinline__ void red_add_v4(float4* addr, float a, float b, float c, float d) {
    asm volatile("red.global.add.v4.f32 [%0], {%1, %2, %3, %4};"
                 :: "l"(addr), "f"(a), "f"(b), "f"(c), "f"(d) : "memory");
}

// deg[i] = 1 (self-loop)
__global__ void k_init_deg(float* deg) {
    int i = blockIdx.x * blockDim.x + threadIdx.x;
    if (i < N_NODES) deg[i] = 1.0f;
}

// degree count on dst (edge_index is int32: row0 = src, row1 = dst)
__global__ void k_deg(const int* __restrict__ dst, int E, float* __restrict__ deg) {
    int e = blockIdx.x * blockDim.x + threadIdx.x;
    if (e < E) {
        unsigned d = (unsigned)dst[e];
        if (d < N_NODES) atomicAdd(&deg[d], 1.0f);
    }
}

// dis[i] = rsqrt(deg); xa[i] = x[i] * dis^2  (self-loop message of layer 1)
__global__ void k_dis_xa(const float4* __restrict__ x,
                         const float* __restrict__ deg,
                         float* __restrict__ dis, float4* __restrict__ xa) {
    int i = blockIdx.x * blockDim.x + threadIdx.x;
    if (i < N_NODES) {
        float di = rsqrtf(deg[i]);
        dis[i] = di;
        float n = di * di;
        float4 xv = x[i];
        xa[i] = make_float4(xv.x * n, xv.y * n, xv.z * n, xv.w * n);
    }
}

// layer-1 scatter on raw 4-dim features (1 thread / edge, one red.v4)
__global__ void k_scatter1(const int* __restrict__ src, const int* __restrict__ dst,
                           const float* __restrict__ dis,
                           const float4* __restrict__ x, float4* __restrict__ xa, int E) {
    int e = blockIdx.x * blockDim.x + threadIdx.x;
    if (e < E) {
        unsigned s = (unsigned)src[e], d = (unsigned)dst[e];
        if (s < N_NODES && d < N_NODES) {
            float n = dis[s] * dis[d];
            float4 v = x[s];
            red_add_v4(xa + d, v.x * n, v.y * n, v.z * n, v.w * n);
        }
    }
}

// h = relu(xa @ W1 + b1) ; agg = h * dis^2 (self-loop seed for layer 2)
__global__ void k_dense1(const float4* __restrict__ xa,
                         const float* __restrict__ W1, const float* __restrict__ b1,
                         const float* __restrict__ dis,
                         float* __restrict__ h, float* __restrict__ agg) {
    int idx = blockIdx.x * blockDim.x + threadIdx.x;
    if (idx < N_NODES * FDIM) {
        int i = idx >> 6;
        int f = idx & 63;
        float4 xv = xa[i];
        float v = xv.x * W1[f] + xv.y * W1[64 + f] + xv.z * W1[128 + f] + xv.w * W1[192 + f] + b1[f];
        v = fmaxf(v, 0.0f);
        h[idx] = v;
        float di = dis[i];
        agg[idx] = v * di * di;
    }
}

// layer-2 scatter: 16 threads / edge, each handles one float4 chunk of the 64-dim row.
// Gather of h[src] and red.v4 to agg[dst] are both 256B-contiguous per edge.
__global__ void k_scatter2(const int* __restrict__ src, const int* __restrict__ dst,
                           const float* __restrict__ dis,
                           const float4* __restrict__ h, float4* __restrict__ agg, int E) {
    int tid = blockIdx.x * blockDim.x + threadIdx.x;
    int e = tid >> 4;
    int c = tid & 15;
    if (e < E) {
        unsigned s = (unsigned)src[e], d = (unsigned)dst[e];
        if (s < N_NODES && d < N_NODES) {
            float n = dis[s] * dis[d];
            float4 v = h[(size_t)s * 16 + c];
            red_add_v4(agg + ((size_t)d * 16 + c), v.x * n, v.y * n, v.z * n, v.w * n);
        }
    }
}

// fused: h2 = relu(agg @ W2 + b2); out = h2 @ Wf + bf
// 256 threads / block = 64 nodes x 4 threads; each thread computes 16 of the 64 hidden outs.
__global__ void k_dense2_final(const float* __restrict__ agg,
                               const float* __restrict__ W2, const float* __restrict__ b2,
                               const float* __restrict__ Wf, const float* __restrict__ bf,
                               float* __restrict__ out) {
    __shared__ float sW2[64 * 64];
    __shared__ float sA [64 * 65];   // +1 pad: conflict-free strided row reads
    __shared__ float sWf[128];
    __shared__ float sb2[64];
    __shared__ float sbf[2];

    int t = threadIdx.x;
    int nodeBase = blockIdx.x * 64;

    for (int i = t; i < 64 * 64; i += 256) sW2[i] = W2[i];
    for (int i = t; i < 128; i += 256)     sWf[i] = Wf[i];
    if (t < 64) sb2[t] = b2[t];
    if (t < 2)  sbf[t] = bf[t];
    for (int i = t; i < 64 * 64; i += 256) {
        int node = i >> 6, k = i & 63;
        int gi = nodeBase + node;
        sA[node * 65 + k] = (gi < N_NODES) ? agg[(size_t)gi * 64 + k] : 0.0f;
    }
    __syncthreads();

    int node = t >> 2;        // 0..63
    int part = t & 3;         // 0..3
    int gi = nodeBase + node;
    float p0 = 0.0f, p1 = 0.0f;
    const float* arow = sA + node * 65;
    int f0 = part * 16;
#pragma unroll
    for (int j = 0; j < 16; ++j) {
        int f = f0 + j;
        float acc = sb2[f];
#pragma unroll
        for (int k = 0; k < 64; ++k)
            acc += arow[k] * sW2[k * 64 + f];
        acc = fmaxf(acc, 0.0f);
        p0 += acc * sWf[f * 2 + 0];
        p1 += acc * sWf[f * 2 + 1];
    }
    // sum the 4 partial threads of each node (adjacent lanes)
    p0 += __shfl_xor_sync(0xFFFFFFFF, p0, 1);
    p0 += __shfl_xor_sync(0xFFFFFFFF, p0, 2);
    p1 += __shfl_xor_sync(0xFFFFFFFF, p1, 1);
    p1 += __shfl_xor_sync(0xFFFFFFFF, p1, 2);
    if (part == 0 && gi < N_NODES) {
        out[(size_t)gi * 2 + 0] = p0 + sbf[0];
        out[(size_t)gi * 2 + 1] = p1 + sbf[1];
    }
}

extern "C" void kernel_launch(void* const* d_in, const int* in_sizes, int n_in,
                              void* d_out, int out_size) {
    const float* x  = (const float*)d_in[0];
    const int*   ei = (const int*)d_in[1];      // int32: JAX x64 disabled
    const float* W1 = (const float*)d_in[2];
    const float* b1 = (const float*)d_in[3];
    const float* W2 = (const float*)d_in[4];
    const float* b2 = (const float*)d_in[5];
    const float* Wf = (const float*)d_in[6];
    const float* bf = (const float*)d_in[7];
    float* out = (float*)d_out;

    int E = in_sizes[1] / 2;
    const int* src = ei;
    const int* dst = ei + E;

    float *deg, *dis;
    float4 *xa, *h, *agg;
    cudaGetSymbolAddress((void**)&deg, g_deg);
    cudaGetSymbolAddress((void**)&dis, g_dis);
    cudaGetSymbolAddress((void**)&xa,  g_xa);
    cudaGetSymbolAddress((void**)&h,   g_h);
    cudaGetSymbolAddress((void**)&agg, g_agg);

    const int B = 256;
    k_init_deg    <<<(N_NODES + B - 1) / B, B>>>(deg);
    k_deg         <<<(E + B - 1) / B, B>>>(dst, E, deg);
    k_dis_xa      <<<(N_NODES + B - 1) / B, B>>>((const float4*)x, deg, dis, xa);
    k_scatter1    <<<(E + B - 1) / B, B>>>(src, dst, dis, (const float4*)x, xa, E);
    k_dense1      <<<(N_NODES * FDIM + B - 1) / B, B>>>(xa, W1, b1, dis, (float*)h, (float*)agg);
    {
        long long work = (long long)E * 16;
        int blocks = (int)((work + B - 1) / B);
        k_scatter2 <<<blocks, B>>>(src, dst, dis, h, agg, E);
    }
    k_dense2_final<<<(N_NODES + 63) / 64, B>>>((const float*)agg, W2, b2, Wf, bf, out);
}

// round 4
// speedup vs baseline: 1.0625x; 1.0625x over previous
#include <cuda_runtime.h>
#include <cstdint>

#define N_NODES 100000
#define FDIM    64

// ---------------- scratch (no allocs allowed) ----------------
__device__ float  g_deg[N_NODES];
__device__ float  g_dis[N_NODES];
__device__ float4 g_xs [N_NODES];          // x[i] * dis[i]  (pre-scaled source features, layer 1)
__device__ float4 g_xa [N_NODES];          // layer-1 accumulator, seeded with xs (self-loop)
__device__ float4 g_h  [N_NODES * 16];     // hs = relu(conv1) * dis  (pre-scaled layer-2 messages)
__device__ float4 g_agg[N_NODES * 16];     // layer-2 accumulator, seeded with hs (self-loop)

__device__ __forceinline__ void red_add_v4(float4* addr, float a, float b, float c, float d) {
    asm volatile("red.global.add.v4.f32 [%0], {%1, %2, %3, %4};"
                 :: "l"(addr), "f"(a), "f"(b), "f"(c), "f"(d) : "memory");
}

// deg[i] = 1 (self-loop)
__global__ void k_init_deg(float* deg) {
    int i = blockIdx.x * blockDim.x + threadIdx.x;
    if (i < N_NODES) deg[i] = 1.0f;
}

// degree count on dst
__global__ void k_deg(const int* __restrict__ dst, int E, float* __restrict__ deg) {
    int e = blockIdx.x * blockDim.x + threadIdx.x;
    if (e < E) {
        unsigned d = (unsigned)dst[e];
        if (d < N_NODES) atomicAdd(&deg[d], 1.0f);
    }
}

// dis = rsqrt(deg); xs = x*dis; xa seeded with xs (self-loop message)
__global__ void k_dis_xs(const float4* __restrict__ x,
                         const float* __restrict__ deg,
                         float* __restrict__ dis,
                         float4* __restrict__ xs, float4* __restrict__ xa) {
    int i = blockIdx.x * blockDim.x + threadIdx.x;
    if (i < N_NODES) {
        float di = rsqrtf(deg[i]);
        dis[i] = di;
        float4 xv = x[i];
        float4 v = make_float4(xv.x * di, xv.y * di, xv.z * di, xv.w * di);
        xs[i] = v;
        xa[i] = v;
    }
}

// layer-1 scatter: xa[d] += xs[s].  No dis loads, no multiplies.
__global__ void k_scatter1(const int* __restrict__ src, const int* __restrict__ dst,
                           const float4* __restrict__ xs, float4* __restrict__ xa, int E) {
    int e = blockIdx.x * blockDim.x + threadIdx.x;
    if (e < E) {
        unsigned s = (unsigned)src[e], d = (unsigned)dst[e];
        if (s < N_NODES && d < N_NODES) {
            float4 v = xs[s];
            red_add_v4(xa + d, v.x, v.y, v.z, v.w);
        }
    }
}

// h = relu(dis*(xa @ W1) + b1); hs = h*dis; store hs to g_h and seed g_agg with hs.
__global__ void k_dense1(const float4* __restrict__ xa,
                         const float* __restrict__ W1, const float* __restrict__ b1,
                         const float* __restrict__ dis,
                         float* __restrict__ hs, float* __restrict__ agg) {
    int idx = blockIdx.x * blockDim.x + threadIdx.x;
    if (idx < N_NODES * FDIM) {
        int i = idx >> 6;
        int f = idx & 63;
        float di = dis[i];
        float4 xv = xa[i];
        float v = (xv.x * W1[f] + xv.y * W1[64 + f] + xv.z * W1[128 + f] + xv.w * W1[192 + f]) * di + b1[f];
        v = fmaxf(v, 0.0f) * di;
        hs[idx] = v;
        agg[idx] = v;
    }
}

// layer-2 scatter: 16 threads / edge, agg[d] += hs[s], pure gather + red.v4.
__global__ void k_scatter2(const int* __restrict__ src, const int* __restrict__ dst,
                           const float4* __restrict__ hs, float4* __restrict__ agg, int E) {
    int tid = blockIdx.x * blockDim.x + threadIdx.x;
    int e = tid >> 4;
    int c = tid & 15;
    if (e < E) {
        unsigned s = (unsigned)src[e], d = (unsigned)dst[e];
        if (s < N_NODES && d < N_NODES) {
            float4 v = hs[(size_t)s * 16 + c];
            red_add_v4(agg + ((size_t)d * 16 + c), v.x, v.y, v.z, v.w);
        }
    }
}

// fused: row = dis[i]*agg[i]; h2 = relu(row @ W2 + b2); out = h2 @ Wf + bf
__global__ void k_dense2_final(const float* __restrict__ agg,
                               const float* __restrict__ dis,
                               const float* __restrict__ W2, const float* __restrict__ b2,
                               const float* __restrict__ Wf, const float* __restrict__ bf,
                               float* __restrict__ out) {
    __shared__ float sW2[64 * 64];
    __shared__ float sA [64 * 65];   // +1 pad: conflict-free strided row reads
    __shared__ float sWf[128];
    __shared__ float sb2[64];
    __shared__ float sbf[2];

    int t = threadIdx.x;
    int nodeBase = blockIdx.x * 64;

    for (int i = t; i < 64 * 64; i += 256) sW2[i] = W2[i];
    for (int i = t; i < 128; i += 256)     sWf[i] = Wf[i];
    if (t < 64) sb2[t] = b2[t];
    if (t < 2)  sbf[t] = bf[t];
    for (int i = t; i < 64 * 64; i += 256) {
        int node = i >> 6, k = i & 63;
        int gi = nodeBase + node;
        sA[node * 65 + k] = (gi < N_NODES) ? agg[(size_t)gi * 64 + k] * dis[gi] : 0.0f;
    }
    __syncthreads();

    int node = t >> 2;        // 0..63
    int part = t & 3;         // 0..3
    int gi = nodeBase + node;
    float p0 = 0.0f, p1 = 0.0f;
    const float* arow = sA + node * 65;
    int f0 = part * 16;
#pragma unroll
    for (int j = 0; j < 16; ++j) {
        int f = f0 + j;
        float acc = sb2[f];
#pragma unroll
        for (int k = 0; k < 64; ++k)
            acc += arow[k] * sW2[k * 64 + f];
        acc = fmaxf(acc, 0.0f);
        p0 += acc * sWf[f * 2 + 0];
        p1 += acc * sWf[f * 2 + 1];
    }
    p0 += __shfl_xor_sync(0xFFFFFFFF, p0, 1);
    p0 += __shfl_xor_sync(0xFFFFFFFF, p0, 2);
    p1 += __shfl_xor_sync(0xFFFFFFFF, p1, 1);
    p1 += __shfl_xor_sync(0xFFFFFFFF, p1, 2);
    if (part == 0 && gi < N_NODES) {
        out[(size_t)gi * 2 + 0] = p0 + sbf[0];
        out[(size_t)gi * 2 + 1] = p1 + sbf[1];
    }
}

extern "C" void kernel_launch(void* const* d_in, const int* in_sizes, int n_in,
                              void* d_out, int out_size) {
    const float* x  = (const float*)d_in[0];
    const int*   ei = (const int*)d_in[1];      // int32: JAX x64 disabled
    const float* W1 = (const float*)d_in[2];
    const float* b1 = (const float*)d_in[3];
    const float* W2 = (const float*)d_in[4];
    const float* b2 = (const float*)d_in[5];
    const float* Wf = (const float*)d_in[6];
    const float* bf = (const float*)d_in[7];
    float* out = (float*)d_out;

    int E = in_sizes[1] / 2;
    const int* src = ei;
    const int* dst = ei + E;

    float *deg, *dis;
    float4 *xs, *xa, *h, *agg;
    cudaGetSymbolAddress((void**)&deg, g_deg);
    cudaGetSymbolAddress((void**)&dis, g_dis);
    cudaGetSymbolAddress((void**)&xs,  g_xs);
    cudaGetSymbolAddress((void**)&xa,  g_xa);
    cudaGetSymbolAddress((void**)&h,   g_h);
    cudaGetSymbolAddress((void**)&agg, g_agg);

    const int B = 256;
    k_init_deg <<<(N_NODES + B - 1) / B, B>>>(deg);
    k_deg      <<<(E + B - 1) / B, B>>>(dst, E, deg);
    k_dis_xs   <<<(N_NODES + B - 1) / B, B>>>((const float4*)x, deg, dis, xs, xa);
    k_scatter1 <<<(E + B - 1) / B, B>>>(src, dst, xs, xa, E);
    k_dense1   <<<(N_NODES * FDIM + B - 1) / B, B>>>(xa, W1, b1, dis, (float*)h, (float*)agg);
    {
        long long work = (long long)E * 16;
        int blocks = (int)((work + B - 1) / B);
        k_scatter2 <<<blocks, B>>>(src, dst, h, agg, E);
    }
    k_dense2_final<<<(N_NODES + 63) / 64, B>>>((const float*)agg, dis, W2, b2, Wf, bf, out);
}